// round 14
// baseline (speedup 1.0000x reference)
#include <cuda_runtime.h>
#include <cuda_fp16.h>
#include <stdint.h>
#include <math.h>

// Problem constants (fixed by the dataset)
#define Bc 8
#define Nc 20000
#define Hc 15
#define Kc 25
#define Gc 64
#define Ec 640000
#define Cc 6
#define Fp 128                      // feature slots per row: b*16 + h, slot h=15 == 0
#define PLANE ((size_t)Nc * Fp)     // elems per plane
#define KP 400                      // padded contraction dim: 25 planes * 16
#define EBLKS 1250                  // einsum blocks (16 nodes each)
#define PBLKS 1776                  // prop grid: 148 SM x 12 resident (one wave)
#define PWARPS (PBLKS * 4)          // persistent warps

struct __align__(8) EdgeT { int c; float w; };

// Scratch (device globals: allocation-free rule).
// INVARIANT: g_deg and g_cursor are all-zero at kernel_launch entry.
// fp32 recursion state: two parity buffers updated IN PLACE (T_k overwrites
// T_{k-2}; each warp touches only its own rows). 20 MB -> L2-resident.
__device__ float  g_TxF[2][PLANE];                        // fp32 parity buffers
__device__ __align__(16) __half g_TxH[Kc][PLANE];         // fp16 planes (128 MB): gather + MMA
__device__ __align__(16) __half g_Wt[Gc * KP];            // W transposed/padded: Wt[g][pl*16+h]
__device__ int    g_deg[Nc];
__device__ float  g_dinv[Nc];
__device__ int    g_rowptr[Nc + 1];
__device__ int    g_cursor[Nc];
__device__ EdgeT  g_csr[Ec];
__device__ float  g_partial[EBLKS * Bc * Cc];

// ---------------------------------------------------------------------------
__global__ void k_deg(const int* __restrict__ ei) {
    int e = blockIdx.x * blockDim.x + threadIdx.x;
    if (e < Ec) atomicAdd(&g_deg[ei[e]], 1);   // row = edge_index[0]
}

// dinv + single-block exclusive scan of g_deg -> g_rowptr.
// Re-zeroes g_deg and g_cursor (restores invariant; cursor consumed below).
__global__ void k_scan_dinv() {
    __shared__ int ss[1024];
    const int CH = 20;
    int tid = threadIdx.x;
    int st = tid * CH;
    int s = 0;
    #pragma unroll
    for (int i = 0; i < CH; i++) {
        int idx = st + i;
        if (idx < Nc) {
            int d = g_deg[idx];
            g_dinv[idx] = (d > 0) ? rsqrtf((float)d) : 0.0f;
            s += d;
        }
    }
    ss[tid] = s;
    __syncthreads();
    for (int off = 1; off < 1024; off <<= 1) {
        int v = (tid >= off) ? ss[tid - off] : 0;
        __syncthreads();
        ss[tid] += v;
        __syncthreads();
    }
    int run = ss[tid] - s;
    for (int i = 0; i < CH; i++) {
        int idx = st + i;
        if (idx < Nc) {
            int d = g_deg[idx];
            g_rowptr[idx] = run;
            run += d;
            g_deg[idx] = 0;
            g_cursor[idx] = 0;
        }
    }
    if (tid == 1023) g_rowptr[Nc] = ss[1023];
}

// Merged: CSR fill (i < Ec) + plane-0 init (i < Nc*Fp) + Wt prep (i < Gc*KP).
// Plane layout: slot f = b*16 + h; h==15 slot is ZERO (K-pad for MMA).
__global__ void k_fill_init(const int* __restrict__ ei, const float* __restrict__ x,
                            const float* __restrict__ W) {
    int i = blockIdx.x * blockDim.x + threadIdx.x;
    if (i < Ec) {
        int r = ei[i];
        int c = ei[Ec + i];
        int pos = g_rowptr[r] + atomicAdd(&g_cursor[r], 1);
        EdgeT t;
        t.c = c;
        t.w = -(g_dinv[r] * g_dinv[c]);   // norm = -(dinv[row]*dinv[col])
        g_csr[pos] = t;
    }
    if (i < Nc * Fp) {
        int n = i >> 7, f = i & 127;
        int b = f >> 4, h = f & 15;
        float v = (h < Hc) ? x[((size_t)b * Nc + n) * Hc + h] : 0.0f;
        g_TxF[0][i] = v;                  // T_0 -> parity-0 buffer
        g_TxH[0][i] = __float2half(v);
    }
    if (i < Gc * KP) {   // Wt[g][pl*16 + h] = W[pl, h, g]; h==15 -> 0
        int g = i / KP, kk = i - g * KP;
        int pl = kk >> 4, h = kk & 15;
        float v = (h < Hc) ? W[((size_t)pl * Hc + h) * Gc + g] : 0.0f;
        g_Wt[i] = __float2half(v);
    }
}

// Warp-per-node CSR gather SpMM: out = (first ? L*in : 2*L*in - prev).
// Persistent-strided: exactly one wave of blocks (1776 x 128); each warp
// processes nodes w, w+PWARPS, ... (kills wave-quantization tail).
// Dual-edge half-warp scheme on 256 B rows; fp16 gather; plain FMA
// accumulation (R13 post-mortem: packed FFMA2 adds serial movs, slower).
__global__ void __launch_bounds__(128) k_prop(int kout, int first) {
    int w0 = blockIdx.x * (blockDim.x >> 5) + (threadIdx.x >> 5);
    int lane = threadIdx.x & 31;
    int grp = lane >> 4;           // which edge of the pair
    int sub = lane & 15;           // uint4 slot within the 256 B row
    const uint4* __restrict__ inh = (const uint4*)g_TxH[kout - 1];
    float4* buf = (float4*)g_TxF[kout & 1];
    uint4* outh = (uint4*)g_TxH[kout];
    for (int warp = w0; warp < Nc; warp += PWARPS) {
        int s = g_rowptr[warp], e = g_rowptr[warp + 1];
        float a0=0.f,a1=0.f,a2=0.f,a3=0.f,a4=0.f,a5=0.f,a6=0.f,a7=0.f;
        int j = s;
        for (; j + 8 <= e; j += 8) {
            EdgeT E[4];
            #pragma unroll
            for (int it = 0; it < 4; it++) E[it] = g_csr[j + 2 * it + grp];
            uint4 V[4];
            #pragma unroll
            for (int it = 0; it < 4; it++)
                V[it] = __ldg(&inh[(size_t)E[it].c * 16 + sub]);
            #pragma unroll
            for (int it = 0; it < 4; it++) {
                float w = E[it].w;
                float2 f0 = __half22float2(*(const __half2*)&V[it].x);
                float2 f1 = __half22float2(*(const __half2*)&V[it].y);
                float2 f2 = __half22float2(*(const __half2*)&V[it].z);
                float2 f3 = __half22float2(*(const __half2*)&V[it].w);
                a0 = fmaf(w, f0.x, a0); a1 = fmaf(w, f0.y, a1);
                a2 = fmaf(w, f1.x, a2); a3 = fmaf(w, f1.y, a3);
                a4 = fmaf(w, f2.x, a4); a5 = fmaf(w, f2.y, a5);
                a6 = fmaf(w, f3.x, a6); a7 = fmaf(w, f3.y, a7);
            }
        }
        for (; j + 2 <= e; j += 2) {
            EdgeT E0 = g_csr[j + grp];
            uint4 V0 = __ldg(&inh[(size_t)E0.c * 16 + sub]);
            float w = E0.w;
            float2 f0 = __half22float2(*(const __half2*)&V0.x);
            float2 f1 = __half22float2(*(const __half2*)&V0.y);
            float2 f2 = __half22float2(*(const __half2*)&V0.z);
            float2 f3 = __half22float2(*(const __half2*)&V0.w);
            a0 = fmaf(w, f0.x, a0); a1 = fmaf(w, f0.y, a1);
            a2 = fmaf(w, f1.x, a2); a3 = fmaf(w, f1.y, a3);
            a4 = fmaf(w, f2.x, a4); a5 = fmaf(w, f2.y, a5);
            a6 = fmaf(w, f3.x, a6); a7 = fmaf(w, f3.y, a7);
        }
        if (j < e && grp == 0) {               // odd trailing edge
            EdgeT E0 = g_csr[j];
            uint4 V0 = __ldg(&inh[(size_t)E0.c * 16 + sub]);
            float w = E0.w;
            float2 f0 = __half22float2(*(const __half2*)&V0.x);
            float2 f1 = __half22float2(*(const __half2*)&V0.y);
            float2 f2 = __half22float2(*(const __half2*)&V0.z);
            float2 f3 = __half22float2(*(const __half2*)&V0.w);
            a0 = fmaf(w, f0.x, a0); a1 = fmaf(w, f0.y, a1);
            a2 = fmaf(w, f1.x, a2); a3 = fmaf(w, f1.y, a3);
            a4 = fmaf(w, f2.x, a4); a5 = fmaf(w, f2.y, a5);
            a6 = fmaf(w, f3.x, a6); a7 = fmaf(w, f3.y, a7);
        }
        a0 += __shfl_down_sync(0xffffffffu, a0, 16);
        a1 += __shfl_down_sync(0xffffffffu, a1, 16);
        a2 += __shfl_down_sync(0xffffffffu, a2, 16);
        a3 += __shfl_down_sync(0xffffffffu, a3, 16);
        a4 += __shfl_down_sync(0xffffffffu, a4, 16);
        a5 += __shfl_down_sync(0xffffffffu, a5, 16);
        a6 += __shfl_down_sync(0xffffffffu, a6, 16);
        a7 += __shfl_down_sync(0xffffffffu, a7, 16);
        if (grp == 0) {
            float4 r0, r1;
            if (first) {
                r0 = make_float4(a0, a1, a2, a3);
                r1 = make_float4(a4, a5, a6, a7);
            } else {
                float4 p0 = buf[(size_t)warp * 32 + 2 * sub];
                float4 p1 = buf[(size_t)warp * 32 + 2 * sub + 1];
                r0.x = fmaf(2.f, a0, -p0.x); r0.y = fmaf(2.f, a1, -p0.y);
                r0.z = fmaf(2.f, a2, -p0.z); r0.w = fmaf(2.f, a3, -p0.w);
                r1.x = fmaf(2.f, a4, -p1.x); r1.y = fmaf(2.f, a5, -p1.y);
                r1.z = fmaf(2.f, a6, -p1.z); r1.w = fmaf(2.f, a7, -p1.w);
            }
            buf[(size_t)warp * 32 + 2 * sub] = r0;
            buf[(size_t)warp * 32 + 2 * sub + 1] = r1;
            uint4 hv;
            *(__half2*)&hv.x = __float22half2_rn(make_float2(r0.x, r0.y));
            *(__half2*)&hv.y = __float22half2_rn(make_float2(r0.z, r0.w));
            *(__half2*)&hv.z = __float22half2_rn(make_float2(r1.x, r1.y));
            *(__half2*)&hv.w = __float22half2_rn(make_float2(r1.z, r1.w));
            outh[(size_t)warp * 16 + sub] = hv;
        }
    }
}

// Tensor-core einsum + relu + FC partial logits.
// GEMM: h[(n,b), g] = sum over 25 k-tiles of A(16x16 fp16) x Wt(16x8 fp16),
// mma.m16n8k16, fp32 accum. Warp tile = 2 nodes (16 rows) x 64 g.
__global__ void __launch_bounds__(256) k_einsum(const float* __restrict__ bias,
                                               const float* __restrict__ fc_w) {
    __shared__ float ps[8][Bc * Cc];
    int tid = threadIdx.x, wid = tid >> 5, lane = tid & 31;
    int lq = lane & 3, lg = lane >> 2;            // quad idx / group id
    int wg = blockIdx.x * 8 + wid;                // global warp id, 0..9999
    int n0 = wg * 2;
    float acc[8][4];
    #pragma unroll
    for (int s = 0; s < 8; s++)
        #pragma unroll
        for (int q = 0; q < 4; q++) acc[s][q] = 0.f;
    size_t rowlo = (size_t)n0 * Fp + lg * 16;     // A row (n0, b=lg)
    int h0 = lq * 2;
    for (int pl = 0; pl < Kc; pl++) {
        const __half* P = g_TxH[pl];
        uint32_t a0 = *(const uint32_t*)(P + rowlo + h0);
        uint32_t a1 = *(const uint32_t*)(P + rowlo + Fp + h0);
        uint32_t a2 = *(const uint32_t*)(P + rowlo + h0 + 8);
        uint32_t a3 = *(const uint32_t*)(P + rowlo + Fp + h0 + 8);
        #pragma unroll
        for (int s = 0; s < 8; s++) {
            const __half* wb = g_Wt + (size_t)(s * 8 + lg) * KP + pl * 16 + h0;
            uint32_t b0 = *(const uint32_t*)(wb);
            uint32_t b1 = *(const uint32_t*)(wb + 8);
            asm volatile(
                "mma.sync.aligned.m16n8k16.row.col.f32.f16.f16.f32 "
                "{%0,%1,%2,%3}, {%4,%5,%6,%7}, {%8,%9}, {%0,%1,%2,%3};"
                : "+f"(acc[s][0]), "+f"(acc[s][1]), "+f"(acc[s][2]), "+f"(acc[s][3])
                : "r"(a0), "r"(a1), "r"(a2), "r"(a3), "r"(b0), "r"(b1));
        }
    }
    float p[Cc];
    #pragma unroll
    for (int c = 0; c < Cc; c++) p[c] = 0.f;
    #pragma unroll
    for (int s = 0; s < 8; s++) {
        int g0 = s * 8 + lq * 2;
        float2 bi = __ldg((const float2*)(bias + g0));
        float hl0 = fmaxf(acc[s][0] + bi.x, 0.f);
        float hl1 = fmaxf(acc[s][1] + bi.y, 0.f);
        float hh0 = fmaxf(acc[s][2] + bi.x, 0.f);
        float hh1 = fmaxf(acc[s][3] + bi.y, 0.f);
        #pragma unroll
        for (int c = 0; c < Cc; c++) {
            const float* fwc = fc_w + (size_t)c * Nc * Gc + (size_t)n0 * Gc + g0;
            float2 wlo = __ldg((const float2*)(fwc));
            float2 whi = __ldg((const float2*)(fwc + Gc));
            p[c] = fmaf(hl0, wlo.x, fmaf(hl1, wlo.y, p[c]));
            p[c] = fmaf(hh0, whi.x, fmaf(hh1, whi.y, p[c]));
        }
    }
    #pragma unroll
    for (int c = 0; c < Cc; c++) {
        p[c] += __shfl_xor_sync(0xffffffffu, p[c], 1);
        p[c] += __shfl_xor_sync(0xffffffffu, p[c], 2);
    }
    if (lq == 0) {
        #pragma unroll
        for (int c = 0; c < Cc; c++) ps[wid][lg * Cc + c] = p[c];
    }
    __syncthreads();
    if (tid < Bc * Cc) {
        float s = 0.f;
        #pragma unroll
        for (int w = 0; w < 8; w++) s += ps[w][tid];
        g_partial[(size_t)blockIdx.x * (Bc * Cc) + tid] = s;
    }
}

// Deterministic reduction of 1250x48 partials + fc_b + log_softmax -> [8,6]
__global__ void k_final(const float* __restrict__ fc_b, float* __restrict__ out) {
    __shared__ float red[480];
    __shared__ float lg[Bc * Cc];
    int t = threadIdx.x;   // 512
    if (t < 480) {
        int col = t % 48, grp = t / 48;   // 10 groups
        float s = 0.f;
        for (int r = grp; r < EBLKS; r += 10)
            s += g_partial[(size_t)r * 48 + col];
        red[t] = s;
    }
    __syncthreads();
    if (t < 48) {
        float s = 0.f;
        #pragma unroll
        for (int g = 0; g < 10; g++) s += red[g * 48 + t];
        lg[t] = s + fc_b[t % Cc];
    }
    __syncthreads();
    if (t < Bc) {
        float m = -1e30f;
        #pragma unroll
        for (int c = 0; c < Cc; c++) m = fmaxf(m, lg[t * Cc + c]);
        float se = 0.f;
        #pragma unroll
        for (int c = 0; c < Cc; c++) se += expf(lg[t * Cc + c] - m);
        float lse = m + logf(se);
        #pragma unroll
        for (int c = 0; c < Cc; c++) out[t * Cc + c] = lg[t * Cc + c] - lse;
    }
}

// ---------------------------------------------------------------------------
extern "C" void kernel_launch(void* const* d_in, const int* in_sizes, int n_in,
                              void* d_out, int out_size) {
    const float* x    = (const float*)d_in[0];   // [B,N,H]
    const int*   ei   = (const int*)d_in[1];     // [2,E]
    const float* W    = (const float*)d_in[2];   // [K,H,G]
    const float* bias = (const float*)d_in[3];   // [G]
    const float* fc_w = (const float*)d_in[4];   // [C, N*G]
    const float* fc_b = (const float*)d_in[5];   // [C]
    float* out = (float*)d_out;                  // [B,C]

    k_deg<<<(Ec + 255) / 256, 256>>>(ei);                        // idx 0
    k_scan_dinv<<<1, 1024>>>();                                  // idx 1
    k_fill_init<<<(Nc * Fp + 255) / 256, 256>>>(ei, x, W);       // idx 2

    // Chebyshev recursion: plane k from fp16 plane k-1; fp32 parity buffers
    k_prop<<<PBLKS, 128>>>(1, 1);                                // idx 3 <- ncu capture
    for (int k = 2; k < Kc; k++)
        k_prop<<<PBLKS, 128>>>(k, 0);

    k_einsum<<<EBLKS, 256>>>(bias, fc_w);
    k_final<<<1, 512>>>(fc_b, out);
}

// round 15
// speedup vs baseline: 1.0263x; 1.0263x over previous
#include <cuda_runtime.h>
#include <cuda_fp16.h>
#include <stdint.h>
#include <math.h>

// Problem constants (fixed by the dataset)
#define Bc 8
#define Nc 20000
#define Hc 15
#define Kc 25
#define Gc 64
#define Ec 640000
#define Cc 6
#define Fp 128                      // feature slots per row: b*16 + h, slot h=15 == 0
#define PLANE ((size_t)Nc * Fp)     // elems per plane
#define KP 400                      // padded contraction dim: 25 planes * 16
#define EBLKS 1250                  // einsum blocks (16 nodes each)

struct __align__(8) EdgeT { int c; float w; };

// Scratch (device globals: allocation-free rule).
// INVARIANT: g_deg and g_cursor are all-zero at kernel_launch entry.
// fp32 recursion state: two parity buffers updated IN PLACE (T_k overwrites
// T_{k-2}; each warp touches only its own row). 20 MB -> L2-resident.
__device__ float  g_TxF[2][PLANE];                        // fp32 parity buffers
__device__ __align__(16) __half g_TxH[Kc][PLANE];         // fp16 planes (128 MB): gather + MMA
__device__ __align__(16) __half g_Wt[Gc * KP];            // W transposed/padded: Wt[g][pl*16+h]
__device__ int    g_deg[Nc];
__device__ float  g_dinv[Nc];
__device__ int    g_rowptr[Nc + 1];
__device__ int    g_cursor[Nc];
__device__ EdgeT  g_csr[Ec];
__device__ float  g_partial[EBLKS * Bc * Cc];

// ---------------------------------------------------------------------------
__global__ void k_deg(const int* __restrict__ ei) {
    int e = blockIdx.x * blockDim.x + threadIdx.x;
    if (e < Ec) atomicAdd(&g_deg[ei[e]], 1);   // row = edge_index[0]
}

// dinv + single-block exclusive scan of g_deg -> g_rowptr.
// Re-zeroes g_deg and g_cursor (restores invariant; cursor consumed below).
__global__ void k_scan_dinv() {
    __shared__ int ss[1024];
    const int CH = 20;
    int tid = threadIdx.x;
    int st = tid * CH;
    int s = 0;
    #pragma unroll
    for (int i = 0; i < CH; i++) {
        int idx = st + i;
        if (idx < Nc) {
            int d = g_deg[idx];
            g_dinv[idx] = (d > 0) ? rsqrtf((float)d) : 0.0f;
            s += d;
        }
    }
    ss[tid] = s;
    __syncthreads();
    for (int off = 1; off < 1024; off <<= 1) {
        int v = (tid >= off) ? ss[tid - off] : 0;
        __syncthreads();
        ss[tid] += v;
        __syncthreads();
    }
    int run = ss[tid] - s;
    for (int i = 0; i < CH; i++) {
        int idx = st + i;
        if (idx < Nc) {
            int d = g_deg[idx];
            g_rowptr[idx] = run;
            run += d;
            g_deg[idx] = 0;
            g_cursor[idx] = 0;
        }
    }
    if (tid == 1023) g_rowptr[Nc] = ss[1023];
}

// Merged, vectorized: CSR fill (i < Ec) + plane-0 init 4 slots/thread
// (i < Nc*Fp/4 == Ec) + Wt prep (i < Gc*KP). Grid = 640K threads.
// Plane layout: slot f = b*16 + h; h==15 slot is ZERO (K-pad for MMA).
__global__ void k_fill_init(const int* __restrict__ ei, const float* __restrict__ x,
                            const float* __restrict__ W) {
    int i = blockIdx.x * blockDim.x + threadIdx.x;
    if (i < Ec) {
        int r = ei[i];
        int c = ei[Ec + i];
        int pos = g_rowptr[r] + atomicAdd(&g_cursor[r], 1);
        EdgeT t;
        t.c = c;
        t.w = -(g_dinv[r] * g_dinv[c]);   // norm = -(dinv[row]*dinv[col])
        g_csr[pos] = t;
    }
    if (i < (int)(PLANE / 4)) {           // 4 consecutive slots, same b
        int n = i >> 5, q = i & 31;       // 32 quads per 128-slot row
        int f0 = q * 4;
        int b = f0 >> 4, h0 = f0 & 15;    // h0 in {0,4,8,12}
        const float* xr = x + ((size_t)b * Nc + n) * Hc + h0;
        float v0 = xr[0];
        float v1 = xr[1];
        float v2 = xr[2];
        float v3 = (h0 == 12) ? 0.0f : xr[3];   // h==15 pad slot
        ((float4*)g_TxF[0])[i] = make_float4(v0, v1, v2, v3);
        uint2 hv;
        *(__half2*)&hv.x = __float22half2_rn(make_float2(v0, v1));
        *(__half2*)&hv.y = __float22half2_rn(make_float2(v2, v3));
        ((uint2*)g_TxH[0])[i] = hv;
    }
    if (i < Gc * KP) {   // Wt[g][pl*16 + h] = W[pl, h, g]; h==15 -> 0
        int g = i / KP, kk = i - g * KP;
        int pl = kk >> 4, h = kk & 15;
        float v = (h < Hc) ? W[((size_t)pl * Hc + h) * Gc + g] : 0.0f;
        g_Wt[i] = __float2half(v);
    }
}

// Warp-per-node CSR gather SpMM: out = (first ? L*in : 2*L*in - prev).
// R12 configuration (best measured): 5000x128 warp-per-node, dual-edge
// half-warp scheme on 256 B rows, fp16 gather, plain FMA accumulation.
__global__ void __launch_bounds__(128) k_prop(int kout, int first) {
    int warp = blockIdx.x * (blockDim.x >> 5) + (threadIdx.x >> 5);
    int lane = threadIdx.x & 31;
    if (warp >= Nc) return;
    int grp = lane >> 4;           // which edge of the pair
    int sub = lane & 15;           // uint4 slot within the 256 B row
    const uint4* __restrict__ inh = (const uint4*)g_TxH[kout - 1];
    int s = g_rowptr[warp], e = g_rowptr[warp + 1];
    float a0=0.f,a1=0.f,a2=0.f,a3=0.f,a4=0.f,a5=0.f,a6=0.f,a7=0.f;
    int j = s;
    for (; j + 8 <= e; j += 8) {
        EdgeT E[4];
        #pragma unroll
        for (int it = 0; it < 4; it++) E[it] = g_csr[j + 2 * it + grp];
        uint4 V[4];
        #pragma unroll
        for (int it = 0; it < 4; it++)
            V[it] = __ldg(&inh[(size_t)E[it].c * 16 + sub]);
        #pragma unroll
        for (int it = 0; it < 4; it++) {
            float w = E[it].w;
            float2 f0 = __half22float2(*(const __half2*)&V[it].x);
            float2 f1 = __half22float2(*(const __half2*)&V[it].y);
            float2 f2 = __half22float2(*(const __half2*)&V[it].z);
            float2 f3 = __half22float2(*(const __half2*)&V[it].w);
            a0 = fmaf(w, f0.x, a0); a1 = fmaf(w, f0.y, a1);
            a2 = fmaf(w, f1.x, a2); a3 = fmaf(w, f1.y, a3);
            a4 = fmaf(w, f2.x, a4); a5 = fmaf(w, f2.y, a5);
            a6 = fmaf(w, f3.x, a6); a7 = fmaf(w, f3.y, a7);
        }
    }
    for (; j + 2 <= e; j += 2) {
        EdgeT E0 = g_csr[j + grp];
        uint4 V0 = __ldg(&inh[(size_t)E0.c * 16 + sub]);
        float w = E0.w;
        float2 f0 = __half22float2(*(const __half2*)&V0.x);
        float2 f1 = __half22float2(*(const __half2*)&V0.y);
        float2 f2 = __half22float2(*(const __half2*)&V0.z);
        float2 f3 = __half22float2(*(const __half2*)&V0.w);
        a0 = fmaf(w, f0.x, a0); a1 = fmaf(w, f0.y, a1);
        a2 = fmaf(w, f1.x, a2); a3 = fmaf(w, f1.y, a3);
        a4 = fmaf(w, f2.x, a4); a5 = fmaf(w, f2.y, a5);
        a6 = fmaf(w, f3.x, a6); a7 = fmaf(w, f3.y, a7);
    }
    if (j < e && grp == 0) {               // odd trailing edge
        EdgeT E0 = g_csr[j];
        uint4 V0 = __ldg(&inh[(size_t)E0.c * 16 + sub]);
        float w = E0.w;
        float2 f0 = __half22float2(*(const __half2*)&V0.x);
        float2 f1 = __half22float2(*(const __half2*)&V0.y);
        float2 f2 = __half22float2(*(const __half2*)&V0.z);
        float2 f3 = __half22float2(*(const __half2*)&V0.w);
        a0 = fmaf(w, f0.x, a0); a1 = fmaf(w, f0.y, a1);
        a2 = fmaf(w, f1.x, a2); a3 = fmaf(w, f1.y, a3);
        a4 = fmaf(w, f2.x, a4); a5 = fmaf(w, f2.y, a5);
        a6 = fmaf(w, f3.x, a6); a7 = fmaf(w, f3.y, a7);
    }
    a0 += __shfl_down_sync(0xffffffffu, a0, 16);
    a1 += __shfl_down_sync(0xffffffffu, a1, 16);
    a2 += __shfl_down_sync(0xffffffffu, a2, 16);
    a3 += __shfl_down_sync(0xffffffffu, a3, 16);
    a4 += __shfl_down_sync(0xffffffffu, a4, 16);
    a5 += __shfl_down_sync(0xffffffffu, a5, 16);
    a6 += __shfl_down_sync(0xffffffffu, a6, 16);
    a7 += __shfl_down_sync(0xffffffffu, a7, 16);
    if (grp != 0) return;
    float4* buf = (float4*)g_TxF[kout & 1];      // prev in, result out (in place)
    uint4* outh = (uint4*)g_TxH[kout];
    float4 r0, r1;
    if (first) {
        r0 = make_float4(a0, a1, a2, a3);
        r1 = make_float4(a4, a5, a6, a7);
    } else {
        float4 p0 = buf[(size_t)warp * 32 + 2 * sub];
        float4 p1 = buf[(size_t)warp * 32 + 2 * sub + 1];
        r0.x = fmaf(2.f, a0, -p0.x); r0.y = fmaf(2.f, a1, -p0.y);
        r0.z = fmaf(2.f, a2, -p0.z); r0.w = fmaf(2.f, a3, -p0.w);
        r1.x = fmaf(2.f, a4, -p1.x); r1.y = fmaf(2.f, a5, -p1.y);
        r1.z = fmaf(2.f, a6, -p1.z); r1.w = fmaf(2.f, a7, -p1.w);
    }
    buf[(size_t)warp * 32 + 2 * sub] = r0;
    buf[(size_t)warp * 32 + 2 * sub + 1] = r1;
    uint4 hv;
    *(__half2*)&hv.x = __float22half2_rn(make_float2(r0.x, r0.y));
    *(__half2*)&hv.y = __float22half2_rn(make_float2(r0.z, r0.w));
    *(__half2*)&hv.z = __float22half2_rn(make_float2(r1.x, r1.y));
    *(__half2*)&hv.w = __float22half2_rn(make_float2(r1.z, r1.w));
    outh[(size_t)warp * 16 + sub] = hv;
}

// Tensor-core einsum + relu + FC partial logits.
// GEMM: h[(n,b), g] = sum over 25 k-tiles of A(16x16 fp16) x Wt(16x8 fp16),
// mma.m16n8k16, fp32 accum. Warp tile = 2 nodes (16 rows) x 64 g.
__global__ void __launch_bounds__(256) k_einsum(const float* __restrict__ bias,
                                               const float* __restrict__ fc_w) {
    __shared__ float ps[8][Bc * Cc];
    int tid = threadIdx.x, wid = tid >> 5, lane = tid & 31;
    int lq = lane & 3, lg = lane >> 2;            // quad idx / group id
    int wg = blockIdx.x * 8 + wid;                // global warp id, 0..9999
    int n0 = wg * 2;
    float acc[8][4];
    #pragma unroll
    for (int s = 0; s < 8; s++)
        #pragma unroll
        for (int q = 0; q < 4; q++) acc[s][q] = 0.f;
    size_t rowlo = (size_t)n0 * Fp + lg * 16;     // A row (n0, b=lg)
    int h0 = lq * 2;
    for (int pl = 0; pl < Kc; pl++) {
        const __half* P = g_TxH[pl];
        uint32_t a0 = *(const uint32_t*)(P + rowlo + h0);
        uint32_t a1 = *(const uint32_t*)(P + rowlo + Fp + h0);
        uint32_t a2 = *(const uint32_t*)(P + rowlo + h0 + 8);
        uint32_t a3 = *(const uint32_t*)(P + rowlo + Fp + h0 + 8);
        #pragma unroll
        for (int s = 0; s < 8; s++) {
            const __half* wb = g_Wt + (size_t)(s * 8 + lg) * KP + pl * 16 + h0;
            uint32_t b0 = *(const uint32_t*)(wb);
            uint32_t b1 = *(const uint32_t*)(wb + 8);
            asm volatile(
                "mma.sync.aligned.m16n8k16.row.col.f32.f16.f16.f32 "
                "{%0,%1,%2,%3}, {%4,%5,%6,%7}, {%8,%9}, {%0,%1,%2,%3};"
                : "+f"(acc[s][0]), "+f"(acc[s][1]), "+f"(acc[s][2]), "+f"(acc[s][3])
                : "r"(a0), "r"(a1), "r"(a2), "r"(a3), "r"(b0), "r"(b1));
        }
    }
    float p[Cc];
    #pragma unroll
    for (int c = 0; c < Cc; c++) p[c] = 0.f;
    #pragma unroll
    for (int s = 0; s < 8; s++) {
        int g0 = s * 8 + lq * 2;
        float2 bi = __ldg((const float2*)(bias + g0));
        float hl0 = fmaxf(acc[s][0] + bi.x, 0.f);
        float hl1 = fmaxf(acc[s][1] + bi.y, 0.f);
        float hh0 = fmaxf(acc[s][2] + bi.x, 0.f);
        float hh1 = fmaxf(acc[s][3] + bi.y, 0.f);
        #pragma unroll
        for (int c = 0; c < Cc; c++) {
            const float* fwc = fc_w + (size_t)c * Nc * Gc + (size_t)n0 * Gc + g0;
            float2 wlo = __ldg((const float2*)(fwc));
            float2 whi = __ldg((const float2*)(fwc + Gc));
            p[c] = fmaf(hl0, wlo.x, fmaf(hl1, wlo.y, p[c]));
            p[c] = fmaf(hh0, whi.x, fmaf(hh1, whi.y, p[c]));
        }
    }
    #pragma unroll
    for (int c = 0; c < Cc; c++) {
        p[c] += __shfl_xor_sync(0xffffffffu, p[c], 1);
        p[c] += __shfl_xor_sync(0xffffffffu, p[c], 2);
    }
    if (lq == 0) {
        #pragma unroll
        for (int c = 0; c < Cc; c++) ps[wid][lg * Cc + c] = p[c];
    }
    __syncthreads();
    if (tid < Bc * Cc) {
        float s = 0.f;
        #pragma unroll
        for (int w = 0; w < 8; w++) s += ps[w][tid];
        g_partial[(size_t)blockIdx.x * (Bc * Cc) + tid] = s;
    }
}

// Deterministic reduction of 1250x48 partials + fc_b + log_softmax -> [8,6]
__global__ void k_final(const float* __restrict__ fc_b, float* __restrict__ out) {
    __shared__ float red[480];
    __shared__ float lg[Bc * Cc];
    int t = threadIdx.x;   // 512
    if (t < 480) {
        int col = t % 48, grp = t / 48;   // 10 groups
        float s = 0.f;
        for (int r = grp; r < EBLKS; r += 10)
            s += g_partial[(size_t)r * 48 + col];
        red[t] = s;
    }
    __syncthreads();
    if (t < 48) {
        float s = 0.f;
        #pragma unroll
        for (int g = 0; g < 10; g++) s += red[g * 48 + t];
        lg[t] = s + fc_b[t % Cc];
    }
    __syncthreads();
    if (t < Bc) {
        float m = -1e30f;
        #pragma unroll
        for (int c = 0; c < Cc; c++) m = fmaxf(m, lg[t * Cc + c]);
        float se = 0.f;
        #pragma unroll
        for (int c = 0; c < Cc; c++) se += expf(lg[t * Cc + c] - m);
        float lse = m + logf(se);
        #pragma unroll
        for (int c = 0; c < Cc; c++) out[t * Cc + c] = lg[t * Cc + c] - lse;
    }
}

// ---------------------------------------------------------------------------
extern "C" void kernel_launch(void* const* d_in, const int* in_sizes, int n_in,
                              void* d_out, int out_size) {
    const float* x    = (const float*)d_in[0];   // [B,N,H]
    const int*   ei   = (const int*)d_in[1];     // [2,E]
    const float* W    = (const float*)d_in[2];   // [K,H,G]
    const float* bias = (const float*)d_in[3];   // [G]
    const float* fc_w = (const float*)d_in[4];   // [C, N*G]
    const float* fc_b = (const float*)d_in[5];   // [C]
    float* out = (float*)d_out;                  // [B,C]

    k_deg<<<(Ec + 255) / 256, 256>>>(ei);                        // idx 0
    k_scan_dinv<<<1, 1024>>>();                                  // idx 1
    k_fill_init<<<(Ec + 255) / 256, 256>>>(ei, x, W);            // idx 2 (640K thr)

    // Chebyshev recursion: plane k from fp16 plane k-1; fp32 parity buffers
    const int PBLK = 128;
    const int PGRID = (Nc + 3) / 4;
    k_prop<<<PGRID, PBLK>>>(1, 1);                               // idx 3 <- ncu capture
    for (int k = 2; k < Kc; k++)
        k_prop<<<PGRID, PBLK>>>(k, 0);

    k_einsum<<<EBLKS, 256>>>(bias, fc_w);
    k_final<<<1, 512>>>(fc_b, out);
}

// round 17
// speedup vs baseline: 1.0596x; 1.0325x over previous
#include <cuda_runtime.h>
#include <cuda_fp16.h>
#include <stdint.h>
#include <math.h>

// Problem constants (fixed by the dataset)
#define Bc 8
#define Nc 20000
#define Hc 15
#define Kc 25
#define Gc 64
#define Ec 640000
#define Cc 6
#define Fp 128                      // feature slots per row: b*16 + h, slot h=15 == 0
#define PLANE ((size_t)Nc * Fp)     // elems per plane
#define KP 400                      // padded contraction dim: 25 planes * 16
#define EBLKS 1250                  // einsum blocks (16 nodes each)

struct __align__(8) EdgeT { int c; float w; };

// Scratch (device globals: allocation-free rule).
// INVARIANT: g_deg and g_cursor are all-zero at kernel_launch entry.
// fp32 recursion state: two parity buffers updated IN PLACE (T_k overwrites
// T_{k-2}; each warp touches only its own row). 20 MB -> L2-resident.
__device__ float  g_TxF[2][PLANE];                        // fp32 parity buffers
__device__ __align__(16) __half g_TxH[Kc][PLANE];         // fp16 planes (128 MB): gather + MMA
__device__ __align__(16) __half g_Wt[Gc * KP];            // W transposed/padded: Wt[g][pl*16+h]
__device__ int    g_deg[Nc];
__device__ float  g_dinv[Nc];
__device__ int    g_rowptr[Nc + 1];
__device__ int    g_cursor[Nc];
__device__ EdgeT  g_csr[Ec];
__device__ float  g_partial[EBLKS * Bc * Cc];

// ---------------------------------------------------------------------------
__global__ void k_deg(const int* __restrict__ ei) {
    int e = blockIdx.x * blockDim.x + threadIdx.x;
    if (e < Ec) atomicAdd(&g_deg[ei[e]], 1);   // row = edge_index[0]
}

// dinv + single-block exclusive scan of g_deg -> g_rowptr.
// Re-zeroes g_deg and g_cursor (restores invariant; cursor consumed below).
__global__ void k_scan_dinv() {
    __shared__ int ss[1024];
    const int CH = 20;
    int tid = threadIdx.x;
    int st = tid * CH;
    int s = 0;
    #pragma unroll
    for (int i = 0; i < CH; i++) {
        int idx = st + i;
        if (idx < Nc) {
            int d = g_deg[idx];
            g_dinv[idx] = (d > 0) ? rsqrtf((float)d) : 0.0f;
            s += d;
        }
    }
    ss[tid] = s;
    __syncthreads();
    for (int off = 1; off < 1024; off <<= 1) {
        int v = (tid >= off) ? ss[tid - off] : 0;
        __syncthreads();
        ss[tid] += v;
        __syncthreads();
    }
    int run = ss[tid] - s;
    for (int i = 0; i < CH; i++) {
        int idx = st + i;
        if (idx < Nc) {
            int d = g_deg[idx];
            g_rowptr[idx] = run;
            run += d;
            g_deg[idx] = 0;
            g_cursor[idx] = 0;
        }
    }
    if (tid == 1023) g_rowptr[Nc] = ss[1023];
}

// Merged, vectorized: CSR fill (i < Ec) + plane-0 init 4 slots/thread
// (i < Nc*Fp/4 == Ec) + Wt prep (i < Gc*KP). Grid = 640K threads.
// Plane layout: slot f = b*16 + h; h==15 slot is ZERO (K-pad for MMA).
__global__ void k_fill_init(const int* __restrict__ ei, const float* __restrict__ x,
                            const float* __restrict__ W) {
    int i = blockIdx.x * blockDim.x + threadIdx.x;
    if (i < Ec) {
        int r = ei[i];
        int c = ei[Ec + i];
        int pos = g_rowptr[r] + atomicAdd(&g_cursor[r], 1);
        EdgeT t;
        t.c = c;
        t.w = -(g_dinv[r] * g_dinv[c]);   // norm = -(dinv[row]*dinv[col])
        g_csr[pos] = t;
    }
    if (i < (int)(PLANE / 4)) {           // 4 consecutive slots, same b
        int n = i >> 5, q = i & 31;       // 32 quads per 128-slot row
        int f0 = q * 4;
        int b = f0 >> 4, h0 = f0 & 15;    // h0 in {0,4,8,12}
        const float* xr = x + ((size_t)b * Nc + n) * Hc + h0;
        float v0 = xr[0];
        float v1 = xr[1];
        float v2 = xr[2];
        float v3 = (h0 == 12) ? 0.0f : xr[3];   // h==15 pad slot
        ((float4*)g_TxF[0])[i] = make_float4(v0, v1, v2, v3);
        uint2 hv;
        *(__half2*)&hv.x = __float22half2_rn(make_float2(v0, v1));
        *(__half2*)&hv.y = __float22half2_rn(make_float2(v2, v3));
        ((uint2*)g_TxH[0])[i] = hv;
    }
    if (i < Gc * KP) {   // Wt[g][pl*16 + h] = W[pl, h, g]; h==15 -> 0
        int g = i / KP, kk = i - g * KP;
        int pl = kk >> 4, h = kk & 15;
        float v = (h < Hc) ? W[((size_t)pl * Hc + h) * Gc + g] : 0.0f;
        g_Wt[i] = __float2half(v);
    }
}

// Warp-per-node CSR gather SpMM: out = (first ? L*in : 2*L*in - prev).
// Dual-edge half-warp scheme on 256 B rows, fp16 gather, plain FMA.
// Software-pipelined CSR stream: next iteration's edge descriptors are
// prefetched right after this iteration's gathers issue, so the CSR L2
// latency overlaps gather latency + FMA work instead of serializing.
__global__ void __launch_bounds__(128) k_prop(int kout, int first) {
    int warp = blockIdx.x * (blockDim.x >> 5) + (threadIdx.x >> 5);
    int lane = threadIdx.x & 31;
    if (warp >= Nc) return;
    int grp = lane >> 4;           // which edge of the pair
    int sub = lane & 15;           // uint4 slot within the 256 B row
    const uint4* __restrict__ inh = (const uint4*)g_TxH[kout - 1];
    int s = g_rowptr[warp], e = g_rowptr[warp + 1];
    float a0=0.f,a1=0.f,a2=0.f,a3=0.f,a4=0.f,a5=0.f,a6=0.f,a7=0.f;
    int j = s;
    EdgeT E[4];
    if (j + 8 <= e) {
        #pragma unroll
        for (int it = 0; it < 4; it++) E[it] = g_csr[j + 2 * it + grp];
    }
    while (j + 8 <= e) {
        // Issue gathers for the current edge batch.
        uint4 V[4];
        #pragma unroll
        for (int it = 0; it < 4; it++)
            V[it] = __ldg(&inh[(size_t)E[it].c * 16 + sub]);
        float wg0 = E[0].w, wg1 = E[1].w, wg2 = E[2].w, wg3 = E[3].w;
        // Prefetch next batch's descriptors (overlaps gather latency).
        int jn = j + 8;
        if (jn + 8 <= e) {
            #pragma unroll
            for (int it = 0; it < 4; it++) E[it] = g_csr[jn + 2 * it + grp];
        }
        {
            float2 f0 = __half22float2(*(const __half2*)&V[0].x);
            float2 f1 = __half22float2(*(const __half2*)&V[0].y);
            float2 f2 = __half22float2(*(const __half2*)&V[0].z);
            float2 f3 = __half22float2(*(const __half2*)&V[0].w);
            a0 = fmaf(wg0, f0.x, a0); a1 = fmaf(wg0, f0.y, a1);
            a2 = fmaf(wg0, f1.x, a2); a3 = fmaf(wg0, f1.y, a3);
            a4 = fmaf(wg0, f2.x, a4); a5 = fmaf(wg0, f2.y, a5);
            a6 = fmaf(wg0, f3.x, a6); a7 = fmaf(wg0, f3.y, a7);
        }
        {
            float2 f0 = __half22float2(*(const __half2*)&V[1].x);
            float2 f1 = __half22float2(*(const __half2*)&V[1].y);
            float2 f2 = __half22float2(*(const __half2*)&V[1].z);
            float2 f3 = __half22float2(*(const __half2*)&V[1].w);
            a0 = fmaf(wg1, f0.x, a0); a1 = fmaf(wg1, f0.y, a1);
            a2 = fmaf(wg1, f1.x, a2); a3 = fmaf(wg1, f1.y, a3);
            a4 = fmaf(wg1, f2.x, a4); a5 = fmaf(wg1, f2.y, a5);
            a6 = fmaf(wg1, f3.x, a6); a7 = fmaf(wg1, f3.y, a7);
        }
        {
            float2 f0 = __half22float2(*(const __half2*)&V[2].x);
            float2 f1 = __half22float2(*(const __half2*)&V[2].y);
            float2 f2 = __half22float2(*(const __half2*)&V[2].z);
            float2 f3 = __half22float2(*(const __half2*)&V[2].w);
            a0 = fmaf(wg2, f0.x, a0); a1 = fmaf(wg2, f0.y, a1);
            a2 = fmaf(wg2, f1.x, a2); a3 = fmaf(wg2, f1.y, a3);
            a4 = fmaf(wg2, f2.x, a4); a5 = fmaf(wg2, f2.y, a5);
            a6 = fmaf(wg2, f3.x, a6); a7 = fmaf(wg2, f3.y, a7);
        }
        {
            float2 f0 = __half22float2(*(const __half2*)&V[3].x);
            float2 f1 = __half22float2(*(const __half2*)&V[3].y);
            float2 f2 = __half22float2(*(const __half2*)&V[3].z);
            float2 f3 = __half22float2(*(const __half2*)&V[3].w);
            a0 = fmaf(wg3, f0.x, a0); a1 = fmaf(wg3, f0.y, a1);
            a2 = fmaf(wg3, f1.x, a2); a3 = fmaf(wg3, f1.y, a3);
            a4 = fmaf(wg3, f2.x, a4); a5 = fmaf(wg3, f2.y, a5);
            a6 = fmaf(wg3, f3.x, a6); a7 = fmaf(wg3, f3.y, a7);
        }
        j = jn;
    }
    for (; j + 2 <= e; j += 2) {
        EdgeT E0 = g_csr[j + grp];
        uint4 V0 = __ldg(&inh[(size_t)E0.c * 16 + sub]);
        float w = E0.w;
        float2 f0 = __half22float2(*(const __half2*)&V0.x);
        float2 f1 = __half22float2(*(const __half2*)&V0.y);
        float2 f2 = __half22float2(*(const __half2*)&V0.z);
        float2 f3 = __half22float2(*(const __half2*)&V0.w);
        a0 = fmaf(w, f0.x, a0); a1 = fmaf(w, f0.y, a1);
        a2 = fmaf(w, f1.x, a2); a3 = fmaf(w, f1.y, a3);
        a4 = fmaf(w, f2.x, a4); a5 = fmaf(w, f2.y, a5);
        a6 = fmaf(w, f3.x, a6); a7 = fmaf(w, f3.y, a7);
    }
    if (j < e && grp == 0) {               // odd trailing edge
        EdgeT E0 = g_csr[j];
        uint4 V0 = __ldg(&inh[(size_t)E0.c * 16 + sub]);
        float w = E0.w;
        float2 f0 = __half22float2(*(const __half2*)&V0.x);
        float2 f1 = __half22float2(*(const __half2*)&V0.y);
        float2 f2 = __half22float2(*(const __half2*)&V0.z);
        float2 f3 = __half22float2(*(const __half2*)&V0.w);
        a0 = fmaf(w, f0.x, a0); a1 = fmaf(w, f0.y, a1);
        a2 = fmaf(w, f1.x, a2); a3 = fmaf(w, f1.y, a3);
        a4 = fmaf(w, f2.x, a4); a5 = fmaf(w, f2.y, a5);
        a6 = fmaf(w, f3.x, a6); a7 = fmaf(w, f3.y, a7);
    }
    a0 += __shfl_down_sync(0xffffffffu, a0, 16);
    a1 += __shfl_down_sync(0xffffffffu, a1, 16);
    a2 += __shfl_down_sync(0xffffffffu, a2, 16);
    a3 += __shfl_down_sync(0xffffffffu, a3, 16);
    a4 += __shfl_down_sync(0xffffffffu, a4, 16);
    a5 += __shfl_down_sync(0xffffffffu, a5, 16);
    a6 += __shfl_down_sync(0xffffffffu, a6, 16);
    a7 += __shfl_down_sync(0xffffffffu, a7, 16);
    if (grp != 0) return;
    float4* buf = (float4*)g_TxF[kout & 1];      // prev in, result out (in place)
    uint4* outh = (uint4*)g_TxH[kout];
    float4 r0, r1;
    if (first) {
        r0 = make_float4(a0, a1, a2, a3);
        r1 = make_float4(a4, a5, a6, a7);
    } else {
        float4 p0 = buf[(size_t)warp * 32 + 2 * sub];
        float4 p1 = buf[(size_t)warp * 32 + 2 * sub + 1];
        r0.x = fmaf(2.f, a0, -p0.x); r0.y = fmaf(2.f, a1, -p0.y);
        r0.z = fmaf(2.f, a2, -p0.z); r0.w = fmaf(2.f, a3, -p0.w);
        r1.x = fmaf(2.f, a4, -p1.x); r1.y = fmaf(2.f, a5, -p1.y);
        r1.z = fmaf(2.f, a6, -p1.z); r1.w = fmaf(2.f, a7, -p1.w);
    }
    buf[(size_t)warp * 32 + 2 * sub] = r0;
    buf[(size_t)warp * 32 + 2 * sub + 1] = r1;
    uint4 hv;
    *(__half2*)&hv.x = __float22half2_rn(make_float2(r0.x, r0.y));
    *(__half2*)&hv.y = __float22half2_rn(make_float2(r0.z, r0.w));
    *(__half2*)&hv.z = __float22half2_rn(make_float2(r1.x, r1.y));
    *(__half2*)&hv.w = __float22half2_rn(make_float2(r1.z, r1.w));
    outh[(size_t)warp * 16 + sub] = hv;
}

// Tensor-core einsum + relu + FC partial logits.
// GEMM: h[(n,b), g] = sum over 25 k-tiles of A(16x16 fp16) x Wt(16x8 fp16),
// mma.m16n8k16, fp32 accum. Warp tile = 2 nodes (16 rows) x 64 g.
__global__ void __launch_bounds__(256) k_einsum(const float* __restrict__ bias,
                                               const float* __restrict__ fc_w) {
    __shared__ float ps[8][Bc * Cc];
    int tid = threadIdx.x, wid = tid >> 5, lane = tid & 31;
    int lq = lane & 3, lg = lane >> 2;            // quad idx / group id
    int wg = blockIdx.x * 8 + wid;                // global warp id, 0..9999
    int n0 = wg * 2;
    float acc[8][4];
    #pragma unroll
    for (int s = 0; s < 8; s++)
        #pragma unroll
        for (int q = 0; q < 4; q++) acc[s][q] = 0.f;
    size_t rowlo = (size_t)n0 * Fp + lg * 16;     // A row (n0, b=lg)
    int h0 = lq * 2;
    for (int pl = 0; pl < Kc; pl++) {
        const __half* P = g_TxH[pl];
        uint32_t a0 = *(const uint32_t*)(P + rowlo + h0);
        uint32_t a1 = *(const uint32_t*)(P + rowlo + Fp + h0);
        uint32_t a2 = *(const uint32_t*)(P + rowlo + h0 + 8);
        uint32_t a3 = *(const uint32_t*)(P + rowlo + Fp + h0 + 8);
        #pragma unroll
        for (int s = 0; s < 8; s++) {
            const __half* wb = g_Wt + (size_t)(s * 8 + lg) * KP + pl * 16 + h0;
            uint32_t b0 = *(const uint32_t*)(wb);
            uint32_t b1 = *(const uint32_t*)(wb + 8);
            asm volatile(
                "mma.sync.aligned.m16n8k16.row.col.f32.f16.f16.f32 "
                "{%0,%1,%2,%3}, {%4,%5,%6,%7}, {%8,%9}, {%0,%1,%2,%3};"
                : "+f"(acc[s][0]), "+f"(acc[s][1]), "+f"(acc[s][2]), "+f"(acc[s][3])
                : "r"(a0), "r"(a1), "r"(a2), "r"(a3), "r"(b0), "r"(b1));
        }
    }
    float p[Cc];
    #pragma unroll
    for (int c = 0; c < Cc; c++) p[c] = 0.f;
    #pragma unroll
    for (int s = 0; s < 8; s++) {
        int g0 = s * 8 + lq * 2;
        float2 bi = __ldg((const float2*)(bias + g0));
        float hl0 = fmaxf(acc[s][0] + bi.x, 0.f);
        float hl1 = fmaxf(acc[s][1] + bi.y, 0.f);
        float hh0 = fmaxf(acc[s][2] + bi.x, 0.f);
        float hh1 = fmaxf(acc[s][3] + bi.y, 0.f);
        #pragma unroll
        for (int c = 0; c < Cc; c++) {
            const float* fwc = fc_w + (size_t)c * Nc * Gc + (size_t)n0 * Gc + g0;
            float2 wlo = __ldg((const float2*)(fwc));
            float2 whi = __ldg((const float2*)(fwc + Gc));
            p[c] = fmaf(hl0, wlo.x, fmaf(hl1, wlo.y, p[c]));
            p[c] = fmaf(hh0, whi.x, fmaf(hh1, whi.y, p[c]));
        }
    }
    #pragma unroll
    for (int c = 0; c < Cc; c++) {
        p[c] += __shfl_xor_sync(0xffffffffu, p[c], 1);
        p[c] += __shfl_xor_sync(0xffffffffu, p[c], 2);
    }
    if (lq == 0) {
        #pragma unroll
        for (int c = 0; c < Cc; c++) ps[wid][lg * Cc + c] = p[c];
    }
    __syncthreads();
    if (tid < Bc * Cc) {
        float s = 0.f;
        #pragma unroll
        for (int w = 0; w < 8; w++) s += ps[w][tid];
        g_partial[(size_t)blockIdx.x * (Bc * Cc) + tid] = s;
    }
}

// Deterministic reduction of 1250x48 partials + fc_b + log_softmax -> [8,6]
__global__ void k_final(const float* __restrict__ fc_b, float* __restrict__ out) {
    __shared__ float red[480];
    __shared__ float lg[Bc * Cc];
    int t = threadIdx.x;   // 512
    if (t < 480) {
        int col = t % 48, grp = t / 48;   // 10 groups
        float s = 0.f;
        for (int r = grp; r < EBLKS; r += 10)
            s += g_partial[(size_t)r * 48 + col];
        red[t] = s;
    }
    __syncthreads();
    if (t < 48) {
        float s = 0.f;
        #pragma unroll
        for (int g = 0; g < 10; g++) s += red[g * 48 + t];
        lg[t] = s + fc_b[t % Cc];
    }
    __syncthreads();
    if (t < Bc) {
        float m = -1e30f;
        #pragma unroll
        for (int c = 0; c < Cc; c++) m = fmaxf(m, lg[t * Cc + c]);
        float se = 0.f;
        #pragma unroll
        for (int c = 0; c < Cc; c++) se += expf(lg[t * Cc + c] - m);
        float lse = m + logf(se);
        #pragma unroll
        for (int c = 0; c < Cc; c++) out[t * Cc + c] = lg[t * Cc + c] - lse;
    }
}

// ---------------------------------------------------------------------------
extern "C" void kernel_launch(void* const* d_in, const int* in_sizes, int n_in,
                              void* d_out, int out_size) {
    const float* x    = (const float*)d_in[0];   // [B,N,H]
    const int*   ei   = (const int*)d_in[1];     // [2,E]
    const float* W    = (const float*)d_in[2];   // [K,H,G]
    const float* bias = (const float*)d_in[3];   // [G]
    const float* fc_w = (const float*)d_in[4];   // [C, N*G]
    const float* fc_b = (const float*)d_in[5];   // [C]
    float* out = (float*)d_out;                  // [B,C]

    k_deg<<<(Ec + 255) / 256, 256>>>(ei);                        // idx 0
    k_scan_dinv<<<1, 1024>>>();                                  // idx 1
    k_fill_init<<<(Ec + 255) / 256, 256>>>(ei, x, W);            // idx 2 (640K thr)

    // Chebyshev recursion: plane k from fp16 plane k-1; fp32 parity buffers
    const int PBLK = 128;
    const int PGRID = (Nc + 3) / 4;
    k_prop<<<PGRID, PBLK>>>(1, 1);                               // idx 3 <- ncu capture
    for (int k = 2; k < Kc; k++)
        k_prop<<<PGRID, PBLK>>>(k, 0);

    k_einsum<<<EBLKS, 256>>>(bias, fc_w);
    k_final<<<1, 512>>>(fc_b, out);
}